// round 14
// baseline (speedup 1.0000x reference)
#include <cuda_runtime.h>
#include <cuda_bf16.h>
#include <cstdint>

// InteractionBlock, persistent warp-specialized HMMA kernel.
//   d_chi = segment_sum(chi^2)                          [n,4]
//   h     = x @ W[0:128,:] + d_chi @ W[128:132,:] + b   [n,132]
//   a1      = h[:, :128]        -> out[0 : n*128]
//   chi_out = h[:,128+seg]*chi  -> out[n*128 : n*128+n*16]
//
// GEMM D[128,144] = A[128,128] @ B[144,128]^T, A/B split bf16 (hi,lo),
// acc = Ah*Bh + Al*Bh + Ah*Bl (fp32). d_chi K-tail exact fp32 in epilogue.
// 12 warps: 8 consumers (MMA+epilogue, 32x72 warp tiles) + 4 producers
// (LDG x/chi -> bf16 split -> STS into the other A buffer). Double-buffered
// A and Dc; ONE __syncthreads per tile; consumers sync privately via
// bar.sync 1. B resides in SMEM for the whole kernel.
// Target plain sm_103 -> mma.sync only.

#define TM       128
#define NPAD     144
#define NCOLS    132
#define THREADS  384
#define NCONS    256              // consumer threads (warps 0..7)
#define B_BYTES  (NPAD * 256)

// ---- SMEM byte layout ----
// A buffer p at p*65536: hi at +0 (32K), lo at +32768 (32K)
#define SM_B_HI   131072
#define SM_B_LO   (131072 + 36864)           // 167936
#define SM_DC     204800                     // 2 x 2048
#define SM_TH     208896                     // 2048
#define SM_WT2    210944                     // [NPAD][4] f32 (2304)
#define SM_BIAS   213248                     // NPAD f32 (576)
#define SMEM_BYTES 213824

__device__ __align__(16) unsigned char g_Bimg[2 * B_BYTES];  // hi then lo
__device__ float g_Wt2[NPAD * 4];
__device__ float g_bias[NPAD];

__device__ __forceinline__ uint32_t smem_u32(const void* p) {
    uint32_t a;
    asm("{ .reg .u64 t; cvta.to.shared.u64 t, %1; cvt.u32.u64 %0, t; }" : "=r"(a) : "l"(p));
    return a;
}
__device__ __forceinline__ uint32_t swoff(uint32_t r, uint32_t b) {
    return r * 256u + ((((b >> 4) ^ (r & 7u)) << 4) | (b & 15u));
}
__device__ __forceinline__ void ldm_x4(uint32_t* r, uint32_t addr) {
    asm volatile("ldmatrix.sync.aligned.m8n8.x4.shared.b16 {%0,%1,%2,%3}, [%4];"
                 : "=r"(r[0]), "=r"(r[1]), "=r"(r[2]), "=r"(r[3]) : "r"(addr));
}
__device__ __forceinline__ void ldm_x2(uint32_t* r, uint32_t addr) {
    asm volatile("ldmatrix.sync.aligned.m8n8.x2.shared.b16 {%0,%1}, [%2];"
                 : "=r"(r[0]), "=r"(r[1]) : "r"(addr));
}
__device__ __forceinline__ void mma16816(float* c, const uint32_t* a, const uint32_t* b) {
    asm volatile(
        "mma.sync.aligned.m16n8k16.row.col.f32.bf16.bf16.f32 "
        "{%0,%1,%2,%3}, {%4,%5,%6,%7}, {%8,%9}, {%0,%1,%2,%3};"
        : "+f"(c[0]), "+f"(c[1]), "+f"(c[2]), "+f"(c[3])
        : "r"(a[0]), "r"(a[1]), "r"(a[2]), "r"(a[3]), "r"(b[0]), "r"(b[1]));
}

// ============================================================================
// Prep kernel: swizzled B image (W^T hi/lo), transposed W tail, bias.
// ============================================================================
__global__ void prep_kernel(const float* __restrict__ W, const float* __restrict__ b) {
    int gid = blockIdx.x * blockDim.x + threadIdx.x;
    int nth = gridDim.x * blockDim.x;
    for (int idx = gid; idx < NPAD * 128; idx += nth) {
        int nrow = idx >> 7;
        int k    = idx & 127;
        float v = (nrow < NCOLS) ? W[k * NCOLS + nrow] : 0.f;
        __nv_bfloat16 hb = __float2bfloat16(v);
        __nv_bfloat16 lb = __float2bfloat16(v - __bfloat162float(hb));
        uint32_t off = swoff((uint32_t)nrow, (uint32_t)k * 2);
        *(__nv_bfloat16*)(g_Bimg + off) = hb;
        *(__nv_bfloat16*)(g_Bimg + B_BYTES + off) = lb;
    }
    for (int c = gid; c < NPAD; c += nth) {
        g_bias[c] = (c < NCOLS) ? b[c] : 0.f;
        #pragma unroll
        for (int s = 0; s < 4; ++s)
            g_Wt2[c * 4 + s] = (c < NCOLS) ? W[(128 + s) * NCOLS + c] : 0.f;
    }
}

// ---- producer: fill A[pbuf] (bf16 hi/lo, swizzled) + Dc[pbuf] for tile ----
__device__ __forceinline__ void produce_tile(const float* __restrict__ x,
                                             const float* __restrict__ chi,
                                             int n, long long row0,
                                             unsigned char* smem, uint32_t sb,
                                             int pbuf, int r /*0..127*/) {
    long long row = row0 + r;
    bool ok = row < n;
    const float* xp = x + row * 128;
    const uint32_t dhi = sb + ((uint32_t)pbuf << 16) + (uint32_t)r * 256u;
    const uint32_t rx7 = (uint32_t)(r & 7);
    #pragma unroll 4
    for (int c = 0; c < 16; ++c) {
        float4 v0 = make_float4(0,0,0,0), v1 = v0;
        if (ok) { v0 = *(const float4*)(xp + c*8); v1 = *(const float4*)(xp + c*8 + 4); }
        float f[8] = {v0.x, v0.y, v0.z, v0.w, v1.x, v1.y, v1.z, v1.w};
        uint32_t hp[4], lp[4];
        #pragma unroll
        for (int q = 0; q < 4; ++q) {
            __nv_bfloat16 h0 = __float2bfloat16(f[2*q]);
            __nv_bfloat16 h1 = __float2bfloat16(f[2*q+1]);
            __nv_bfloat16 l0 = __float2bfloat16(f[2*q]   - __bfloat162float(h0));
            __nv_bfloat16 l1 = __float2bfloat16(f[2*q+1] - __bfloat162float(h1));
            hp[q] = (uint32_t)__bfloat16_as_ushort(h0) | ((uint32_t)__bfloat16_as_ushort(h1) << 16);
            lp[q] = (uint32_t)__bfloat16_as_ushort(l0) | ((uint32_t)__bfloat16_as_ushort(l1) << 16);
        }
        uint32_t a = dhi + ((((uint32_t)c ^ rx7)) << 4);
        asm volatile("st.shared.v4.b32 [%0], {%1,%2,%3,%4};"
                     :: "r"(a), "r"(hp[0]), "r"(hp[1]), "r"(hp[2]), "r"(hp[3]));
        asm volatile("st.shared.v4.b32 [%0], {%1,%2,%3,%4};"
                     :: "r"(a + 32768u), "r"(lp[0]), "r"(lp[1]), "r"(lp[2]), "r"(lp[3]));
    }
    // chi -> d_chi
    float4 c0 = make_float4(0,0,0,0), c1 = c0, c2 = c0, c3 = c0;
    if (ok) {
        const float4* cp = (const float4*)(chi + row * 16);
        c0 = cp[0]; c1 = cp[1]; c2 = cp[2]; c3 = cp[3];
    }
    float d0 = c0.x*c0.x;
    float d1 = c0.y*c0.y + c0.z*c0.z + c0.w*c0.w;
    float d2 = c1.x*c1.x + c1.y*c1.y + c1.z*c1.z + c1.w*c1.w + c2.x*c2.x;
    float d3 = c2.y*c2.y + c2.z*c2.z + c2.w*c2.w
             + c3.x*c3.x + c3.y*c3.y + c3.z*c3.z + c3.w*c3.w;
    *(float4*)(smem + SM_DC + pbuf * 2048 + r * 16) = make_float4(d0, d1, d2, d3);
}

// ============================================================================
// Main persistent kernel
// ============================================================================
__global__ __launch_bounds__(THREADS, 1)
void ib_pk(const float* __restrict__ x,
           const float* __restrict__ chi,
           float* __restrict__ out,
           int n, int ntiles)
{
    extern __shared__ __align__(16) unsigned char smem[];
    const uint32_t sb = smem_u32(smem);
    const int tid = threadIdx.x;
    const int wid = tid >> 5;
    const int lid = tid & 31;
    const bool consumer = (tid < NCONS);

    // ---- one-time B image + tail/bias (L2-hot) ----
    {
        const uint4* src = (const uint4*)g_Bimg;
        uint4* dst = (uint4*)(smem + SM_B_HI);
        for (int i = tid; i < (2 * B_BYTES) / 16; i += THREADS) dst[i] = src[i];
        float* wt = (float*)(smem + SM_WT2);
        for (int i = tid; i < 4 * NPAD; i += THREADS) wt[i] = g_Wt2[i];
        if (tid < NPAD) ((float*)(smem + SM_BIAS))[tid] = g_bias[tid];
    }

    int t = blockIdx.x;
    int p = 0;

    // ---- prologue: producers fill A[0]/Dc[0] for tile t ----
    if (!consumer)
        produce_tile(x, chi, n, (long long)t * TM, smem, sb, 0, tid - NCONS);
    __syncthreads();

    // consumer tiling: 4 row-groups (mt=2 -> 32 rows) x 2 col-groups (72)
    const int m0 = (wid & 3) * 32;
    const int n0 = (wid >> 2) * 72;
    const uint32_t rx = (uint32_t)(lid & 7);
    const uint32_t arow_off = (uint32_t)(m0 + (lid & 15)) * 256u;
    const uint32_t ahalf = (uint32_t)((lid >> 4) & 1);   // A k-chunk lane select (bit 4)
    const uint32_t khalf = (uint32_t)((lid >> 3) & 1);   // B k-chunk lane select (bit 3)
    const uint32_t b_base  = sb + SM_B_HI + (uint32_t)(n0 + (int)ahalf * 8 + (lid & 7)) * 256;
    const uint32_t b2_base = sb + SM_B_HI + (uint32_t)(n0 + 64 + (lid & 7)) * 256;
    const int tr = lid >> 2;
    const int tc = (lid & 3) * 2;

    const float* Bs  = (const float*)(smem + SM_BIAS);
    const float* Wt2 = (const float*)(smem + SM_WT2);
    float* out1 = out;
    float* out2 = out + (long long)n * 128;

    while (t < ntiles) {
        const long long row0 = (long long)t * TM;
        const int tn = t + gridDim.x;

        if (consumer) {
            const uint32_t abase = sb + ((uint32_t)p << 16) + arow_off;

            float acc[2][9][4];
            #pragma unroll
            for (int mt = 0; mt < 2; ++mt)
                #pragma unroll
                for (int nt = 0; nt < 9; ++nt)
                    #pragma unroll
                    for (int q = 0; q < 4; ++q) acc[mt][nt][q] = 0.f;

            #pragma unroll
            for (int k = 0; k < 8; ++k) {
                uint32_t ah[2][4], al[2][4], bb[9][2];
                // A: 16x16 fragment; k-chunk selected by lane bit 4 (ahalf)
                const uint32_t ac = (((uint32_t)(2 * k) + ahalf) ^ rx) << 4;
                #pragma unroll
                for (int mt = 0; mt < 2; ++mt) {
                    uint32_t a = abase + (uint32_t)mt * 4096 + ac;
                    ldm_x4(ah[mt], a);
                    ldm_x4(al[mt], a + 32768u);
                }
                // B: k-chunk selected by lane bit 3 (khalf) -- NOT ahalf
                const uint32_t bc = (((uint32_t)(2 * k) + khalf) ^ rx) << 4;
                // B hi fragments
                #pragma unroll
                for (int p4 = 0; p4 < 4; ++p4) {
                    uint32_t r4[4];
                    ldm_x4(r4, b_base + (uint32_t)p4 * 4096 + bc);
                    bb[2*p4][0] = r4[0]; bb[2*p4][1] = r4[1];
                    bb[2*p4+1][0] = r4[2]; bb[2*p4+1][1] = r4[3];
                }
                if (n0 == 0) ldm_x2(bb[8], b2_base + bc);
                // pass1: Ah*Bh
                #pragma unroll
                for (int nt = 0; nt < 9; ++nt)
                    if (nt < 8 || n0 == 0) {
                        mma16816(acc[0][nt], ah[0], bb[nt]);
                        mma16816(acc[1][nt], ah[1], bb[nt]);
                    }
                // pass2: Al*Bh
                #pragma unroll
                for (int nt = 0; nt < 9; ++nt)
                    if (nt < 8 || n0 == 0) {
                        mma16816(acc[0][nt], al[0], bb[nt]);
                        mma16816(acc[1][nt], al[1], bb[nt]);
                    }
                // B lo fragments (reuse bb regs)
                #pragma unroll
                for (int p4 = 0; p4 < 4; ++p4) {
                    uint32_t r4[4];
                    ldm_x4(r4, b_base + (SM_B_LO - SM_B_HI) + (uint32_t)p4 * 4096 + bc);
                    bb[2*p4][0] = r4[0]; bb[2*p4][1] = r4[1];
                    bb[2*p4+1][0] = r4[2]; bb[2*p4+1][1] = r4[3];
                }
                if (n0 == 0) ldm_x2(bb[8], b2_base + (SM_B_LO - SM_B_HI) + bc);
                // pass3: Ah*Bl
                #pragma unroll
                for (int nt = 0; nt < 9; ++nt)
                    if (nt < 8 || n0 == 0) {
                        mma16816(acc[0][nt], ah[0], bb[nt]);
                        mma16816(acc[1][nt], ah[1], bb[nt]);
                    }
            }

            // ---- epilogue: bias + exact d_chi tail; a1 -> gmem, 128..131 -> Th ----
            {
                const float* Dc = (const float*)(smem + SM_DC + p * 2048);
                float* Th = (float*)(smem + SM_TH);
                #pragma unroll
                for (int mt = 0; mt < 2; ++mt) {
                    const int r = m0 + mt * 16 + tr;
                    const long long rowA = row0 + r;
                    const long long rowB = rowA + 8;
                    const float4 dca = *(const float4*)&Dc[r * 4];
                    const float4 dcb = *(const float4*)&Dc[(r + 8) * 4];
                    #pragma unroll
                    for (int nt = 0; nt < 9; ++nt) {
                        const int c = n0 + nt * 8 + tc;
                        if (c < NCOLS) {
                            float2 bi = *(const float2*)&Bs[c];
                            float4 w0 = *(const float4*)&Wt2[c * 4];
                            float4 w1 = *(const float4*)&Wt2[(c + 1) * 4];
                            float h0 = acc[mt][nt][0] + bi.x;
                            float h1 = acc[mt][nt][1] + bi.y;
                            float h2 = acc[mt][nt][2] + bi.x;
                            float h3 = acc[mt][nt][3] + bi.y;
                            h0 = fmaf(dca.x, w0.x, h0); h0 = fmaf(dca.y, w0.y, h0);
                            h0 = fmaf(dca.z, w0.z, h0); h0 = fmaf(dca.w, w0.w, h0);
                            h1 = fmaf(dca.x, w1.x, h1); h1 = fmaf(dca.y, w1.y, h1);
                            h1 = fmaf(dca.z, w1.z, h1); h1 = fmaf(dca.w, w1.w, h1);
                            h2 = fmaf(dcb.x, w0.x, h2); h2 = fmaf(dcb.y, w0.y, h2);
                            h2 = fmaf(dcb.z, w0.z, h2); h2 = fmaf(dcb.w, w0.w, h2);
                            h3 = fmaf(dcb.x, w1.x, h3); h3 = fmaf(dcb.y, w1.y, h3);
                            h3 = fmaf(dcb.z, w1.z, h3); h3 = fmaf(dcb.w, w1.w, h3);
                            if (c < 128) {
                                if (rowA < n) *(float2*)(out1 + rowA * 128 + c) = make_float2(h0, h1);
                                if (rowB < n) *(float2*)(out1 + rowB * 128 + c) = make_float2(h2, h3);
                            } else {
                                *(float2*)&Th[r * 4 + (c - 128)]       = make_float2(h0, h1);
                                *(float2*)&Th[(r + 8) * 4 + (c - 128)] = make_float2(h2, h3);
                            }
                        }
                    }
                }
            }
            // consumers-only barrier: Th complete
            asm volatile("bar.sync 1, %0;" :: "n"(NCONS) : "memory");

            // ---- chi_out (chi LDG, L2-hot) ----
            {
                const float* Th = (const float*)(smem + SM_TH);
                #pragma unroll
                for (int it = 0; it < 8; ++it) {
                    int i = tid + NCONS * it;     // 0..2047
                    int r = i >> 4;
                    int m = i & 15;
                    long long row = row0 + r;
                    if (row < n) {
                        int s = (m == 0) ? 0 : (m < 4) ? 1 : (m < 9) ? 2 : 3;
                        out2[row * 16 + m] = Th[r * 4 + s] * chi[row * 16 + m];
                    }
                }
            }
        } else {
            // ---- producers: fill the other buffer with tile t+grid ----
            if (tn < ntiles)
                produce_tile(x, chi, n, (long long)tn * TM, smem, sb, p ^ 1, tid - NCONS);
        }

        __syncthreads();
        p ^= 1;
        t = tn;
    }
}

extern "C" void kernel_launch(void* const* d_in, const int* in_sizes, int n_in,
                              void* d_out, int out_size)
{
    const float* x   = (const float*)d_in[0];
    const float* chi = (const float*)d_in[1];
    // d_in[2] = point_mask (unused by reference computation)
    const float* W   = (const float*)d_in[3];
    const float* b   = (const float*)d_in[4];
    float* out = (float*)d_out;

    const int n = in_sizes[2];
    const int ntiles = (n + TM - 1) / TM;

    int dev = 0, nsm = 148;
    cudaGetDevice(&dev);
    cudaDeviceGetAttribute(&nsm, cudaDevAttrMultiProcessorCount, dev);

    cudaFuncSetAttribute(ib_pk,
                         cudaFuncAttributeMaxDynamicSharedMemorySize, SMEM_BYTES);

    prep_kernel<<<64, 256>>>(W, b);
    int grid = ntiles < nsm ? ntiles : nsm;
    ib_pk<<<grid, THREADS, SMEM_BYTES>>>(x, chi, out, n, ntiles);
}

// round 15
// speedup vs baseline: 1.6039x; 1.6039x over previous
#include <cuda_runtime.h>
#include <cuda_bf16.h>
#include <cstdint>

// InteractionBlock, persistent warp-specialized HMMA kernel (coalesced producer).
//   d_chi = segment_sum(chi^2)                          [n,4]
//   h     = x @ W[0:128,:] + d_chi @ W[128:132,:] + b   [n,132]
//   a1      = h[:, :128]        -> out[0 : n*128]
//   chi_out = h[:,128+seg]*chi  -> out[n*128 : n*128+n*16]
//
// GEMM D[128,144] = A[128,128] @ B[144,128]^T, A/B split bf16 (hi,lo),
// acc = Ah*Bh + Al*Bh + Ah*Bl (fp32). d_chi K-tail exact fp32 in epilogue.
// 12 warps: 8 consumers (MMA+epilogue, 32x72 warp tiles) + 4 producers
// (coalesced LDG x/chi -> bf16 split -> STS into other A buffer).
// Double-buffered A and Dc; ONE __syncthreads per tile; consumers sync
// privately via bar.sync 1. B resides in SMEM for the whole kernel.
// Target plain sm_103 -> mma.sync only.

#define TM       128
#define NPAD     144
#define NCOLS    132
#define THREADS  384
#define NCONS    256              // consumer threads (warps 0..7)
#define B_BYTES  (NPAD * 256)

// ---- SMEM byte layout ----
// A buffer p at p*65536: hi at +0 (32K), lo at +32768 (32K)
#define SM_B_HI   131072
#define SM_B_LO   (131072 + 36864)           // 167936
#define SM_DC     204800                     // 2 x 2048
#define SM_TH     208896                     // 2048
#define SM_WT2    210944                     // [NPAD][4] f32 (2304)
#define SM_BIAS   213248                     // NPAD f32 (576)
#define SMEM_BYTES 213824

__device__ __align__(16) unsigned char g_Bimg[2 * B_BYTES];  // hi then lo
__device__ float g_Wt2[NPAD * 4];
__device__ float g_bias[NPAD];

__device__ __forceinline__ uint32_t smem_u32(const void* p) {
    uint32_t a;
    asm("{ .reg .u64 t; cvta.to.shared.u64 t, %1; cvt.u32.u64 %0, t; }" : "=r"(a) : "l"(p));
    return a;
}
__device__ __forceinline__ uint32_t swoff(uint32_t r, uint32_t b) {
    return r * 256u + ((((b >> 4) ^ (r & 7u)) << 4) | (b & 15u));
}
__device__ __forceinline__ void ldm_x4(uint32_t* r, uint32_t addr) {
    asm volatile("ldmatrix.sync.aligned.m8n8.x4.shared.b16 {%0,%1,%2,%3}, [%4];"
                 : "=r"(r[0]), "=r"(r[1]), "=r"(r[2]), "=r"(r[3]) : "r"(addr));
}
__device__ __forceinline__ void ldm_x2(uint32_t* r, uint32_t addr) {
    asm volatile("ldmatrix.sync.aligned.m8n8.x2.shared.b16 {%0,%1}, [%2];"
                 : "=r"(r[0]), "=r"(r[1]) : "r"(addr));
}
__device__ __forceinline__ void mma16816(float* c, const uint32_t* a, const uint32_t* b) {
    asm volatile(
        "mma.sync.aligned.m16n8k16.row.col.f32.bf16.bf16.f32 "
        "{%0,%1,%2,%3}, {%4,%5,%6,%7}, {%8,%9}, {%0,%1,%2,%3};"
        : "+f"(c[0]), "+f"(c[1]), "+f"(c[2]), "+f"(c[3])
        : "r"(a[0]), "r"(a[1]), "r"(a[2]), "r"(a[3]), "r"(b[0]), "r"(b[1]));
}

// ============================================================================
// Prep kernel: swizzled B image (W^T hi/lo), transposed W tail, bias.
// ============================================================================
__global__ void prep_kernel(const float* __restrict__ W, const float* __restrict__ b) {
    int gid = blockIdx.x * blockDim.x + threadIdx.x;
    int nth = gridDim.x * blockDim.x;
    for (int idx = gid; idx < NPAD * 128; idx += nth) {
        int nrow = idx >> 7;
        int k    = idx & 127;
        float v = (nrow < NCOLS) ? W[k * NCOLS + nrow] : 0.f;
        __nv_bfloat16 hb = __float2bfloat16(v);
        __nv_bfloat16 lb = __float2bfloat16(v - __bfloat162float(hb));
        uint32_t off = swoff((uint32_t)nrow, (uint32_t)k * 2);
        *(__nv_bfloat16*)(g_Bimg + off) = hb;
        *(__nv_bfloat16*)(g_Bimg + B_BYTES + off) = lb;
    }
    for (int c = gid; c < NPAD; c += nth) {
        g_bias[c] = (c < NCOLS) ? b[c] : 0.f;
        #pragma unroll
        for (int s = 0; s < 4; ++s)
            g_Wt2[c * 4 + s] = (c < NCOLS) ? W[(128 + s) * NCOLS + c] : 0.f;
    }
}

// ---- producer: fill A[pbuf] (bf16 hi/lo, swizzled) + Dc[pbuf] for tile ----
// COALESCED: thread owns fixed float-column c4 = (ptid&31)*4, walks rows
// r = (ptid>>5) + 4*it. Warp-LDG.128 covers 32 consecutive chunks of one
// row -> 4 L1 lines per instruction (vs 32 with row-per-thread).
__device__ __forceinline__ void produce_tile(const float* __restrict__ x,
                                             const float* __restrict__ chi,
                                             int n, long long row0,
                                             unsigned char* smem, uint32_t sb,
                                             int pbuf, int ptid /*0..127*/) {
    const uint32_t base = sb + ((uint32_t)pbuf << 16);
    const int c4   = (ptid & 31) << 2;            // float col 0,4,..,124
    const int r0   = ptid >> 5;                   // 0..3
    const uint32_t coff = (uint32_t)(c4 * 2);     // byte col in bf16 row

    #pragma unroll
    for (int it = 0; it < 32; ++it) {
        int r = r0 + (it << 2);
        long long row = row0 + r;
        float4 v = make_float4(0.f, 0.f, 0.f, 0.f);
        if (row < n) v = *(const float4*)(x + row * 128 + c4);
        __nv_bfloat16 h0 = __float2bfloat16(v.x);
        __nv_bfloat16 h1 = __float2bfloat16(v.y);
        __nv_bfloat16 h2 = __float2bfloat16(v.z);
        __nv_bfloat16 h3 = __float2bfloat16(v.w);
        __nv_bfloat16 l0 = __float2bfloat16(v.x - __bfloat162float(h0));
        __nv_bfloat16 l1 = __float2bfloat16(v.y - __bfloat162float(h1));
        __nv_bfloat16 l2 = __float2bfloat16(v.z - __bfloat162float(h2));
        __nv_bfloat16 l3 = __float2bfloat16(v.w - __bfloat162float(h3));
        uint32_t hp0 = (uint32_t)__bfloat16_as_ushort(h0) | ((uint32_t)__bfloat16_as_ushort(h1) << 16);
        uint32_t hp1 = (uint32_t)__bfloat16_as_ushort(h2) | ((uint32_t)__bfloat16_as_ushort(h3) << 16);
        uint32_t lp0 = (uint32_t)__bfloat16_as_ushort(l0) | ((uint32_t)__bfloat16_as_ushort(l1) << 16);
        uint32_t lp1 = (uint32_t)__bfloat16_as_ushort(l2) | ((uint32_t)__bfloat16_as_ushort(l3) << 16);
        uint32_t a = base + swoff((uint32_t)r, coff);
        asm volatile("st.shared.v2.b32 [%0], {%1,%2};"
                     :: "r"(a), "r"(hp0), "r"(hp1));
        asm volatile("st.shared.v2.b32 [%0], {%1,%2};"
                     :: "r"(a + 32768u), "r"(lp0), "r"(lp1));
    }

    // chi -> d_chi (row-per-thread; tiny volume)
    long long rowc = row0 + ptid;
    float4 c0 = make_float4(0,0,0,0), c1 = c0, c2 = c0, c3 = c0;
    if (rowc < n) {
        const float4* cp = (const float4*)(chi + rowc * 16);
        c0 = cp[0]; c1 = cp[1]; c2 = cp[2]; c3 = cp[3];
    }
    float d0 = c0.x*c0.x;
    float d1 = c0.y*c0.y + c0.z*c0.z + c0.w*c0.w;
    float d2 = c1.x*c1.x + c1.y*c1.y + c1.z*c1.z + c1.w*c1.w + c2.x*c2.x;
    float d3 = c2.y*c2.y + c2.z*c2.z + c2.w*c2.w
             + c3.x*c3.x + c3.y*c3.y + c3.z*c3.z + c3.w*c3.w;
    *(float4*)(smem + SM_DC + pbuf * 2048 + ptid * 16) = make_float4(d0, d1, d2, d3);
}

// ============================================================================
// Main persistent kernel
// ============================================================================
__global__ __launch_bounds__(THREADS, 1)
void ib_pk(const float* __restrict__ x,
           const float* __restrict__ chi,
           float* __restrict__ out,
           int n, int ntiles)
{
    extern __shared__ __align__(16) unsigned char smem[];
    const uint32_t sb = smem_u32(smem);
    const int tid = threadIdx.x;
    const int wid = tid >> 5;
    const int lid = tid & 31;
    const bool consumer = (tid < NCONS);

    // ---- one-time B image + tail/bias (L2-hot) ----
    {
        const uint4* src = (const uint4*)g_Bimg;
        uint4* dst = (uint4*)(smem + SM_B_HI);
        for (int i = tid; i < (2 * B_BYTES) / 16; i += THREADS) dst[i] = src[i];
        float* wt = (float*)(smem + SM_WT2);
        for (int i = tid; i < 4 * NPAD; i += THREADS) wt[i] = g_Wt2[i];
        if (tid < NPAD) ((float*)(smem + SM_BIAS))[tid] = g_bias[tid];
    }

    int t = blockIdx.x;
    int p = 0;

    // ---- prologue: producers fill A[0]/Dc[0] for tile t ----
    if (!consumer)
        produce_tile(x, chi, n, (long long)t * TM, smem, sb, 0, tid - NCONS);
    __syncthreads();

    // consumer tiling: 4 row-groups (mt=2 -> 32 rows) x 2 col-groups (72)
    const int m0 = (wid & 3) * 32;
    const int n0 = (wid >> 2) * 72;
    const uint32_t rx = (uint32_t)(lid & 7);
    const uint32_t arow_off = (uint32_t)(m0 + (lid & 15)) * 256u;
    const uint32_t ahalf = (uint32_t)((lid >> 4) & 1);   // A k-chunk lane select (bit 4)
    const uint32_t khalf = (uint32_t)((lid >> 3) & 1);   // B k-chunk lane select (bit 3)
    const uint32_t b_base  = sb + SM_B_HI + (uint32_t)(n0 + (int)ahalf * 8 + (lid & 7)) * 256;
    const uint32_t b2_base = sb + SM_B_HI + (uint32_t)(n0 + 64 + (lid & 7)) * 256;
    const int tr = lid >> 2;
    const int tc = (lid & 3) * 2;

    const float* Bs  = (const float*)(smem + SM_BIAS);
    const float* Wt2 = (const float*)(smem + SM_WT2);
    float* out1 = out;
    float* out2 = out + (long long)n * 128;

    while (t < ntiles) {
        const long long row0 = (long long)t * TM;
        const int tn = t + gridDim.x;

        if (consumer) {
            const uint32_t abase = sb + ((uint32_t)p << 16) + arow_off;

            float acc[2][9][4];
            #pragma unroll
            for (int mt = 0; mt < 2; ++mt)
                #pragma unroll
                for (int nt = 0; nt < 9; ++nt)
                    #pragma unroll
                    for (int q = 0; q < 4; ++q) acc[mt][nt][q] = 0.f;

            #pragma unroll
            for (int k = 0; k < 8; ++k) {
                uint32_t ah[2][4], al[2][4], bb[9][2];
                // A: 16x16 fragment; k-chunk selected by lane bit 4 (ahalf)
                const uint32_t ac = (((uint32_t)(2 * k) + ahalf) ^ rx) << 4;
                #pragma unroll
                for (int mt = 0; mt < 2; ++mt) {
                    uint32_t a = abase + (uint32_t)mt * 4096 + ac;
                    ldm_x4(ah[mt], a);
                    ldm_x4(al[mt], a + 32768u);
                }
                // B: k-chunk selected by lane bit 3 (khalf)
                const uint32_t bc = (((uint32_t)(2 * k) + khalf) ^ rx) << 4;
                // B hi fragments
                #pragma unroll
                for (int p4 = 0; p4 < 4; ++p4) {
                    uint32_t r4[4];
                    ldm_x4(r4, b_base + (uint32_t)p4 * 4096 + bc);
                    bb[2*p4][0] = r4[0]; bb[2*p4][1] = r4[1];
                    bb[2*p4+1][0] = r4[2]; bb[2*p4+1][1] = r4[3];
                }
                if (n0 == 0) ldm_x2(bb[8], b2_base + bc);
                // pass1: Ah*Bh
                #pragma unroll
                for (int nt = 0; nt < 9; ++nt)
                    if (nt < 8 || n0 == 0) {
                        mma16816(acc[0][nt], ah[0], bb[nt]);
                        mma16816(acc[1][nt], ah[1], bb[nt]);
                    }
                // pass2: Al*Bh
                #pragma unroll
                for (int nt = 0; nt < 9; ++nt)
                    if (nt < 8 || n0 == 0) {
                        mma16816(acc[0][nt], al[0], bb[nt]);
                        mma16816(acc[1][nt], al[1], bb[nt]);
                    }
                // B lo fragments (reuse bb regs)
                #pragma unroll
                for (int p4 = 0; p4 < 4; ++p4) {
                    uint32_t r4[4];
                    ldm_x4(r4, b_base + (SM_B_LO - SM_B_HI) + (uint32_t)p4 * 4096 + bc);
                    bb[2*p4][0] = r4[0]; bb[2*p4][1] = r4[1];
                    bb[2*p4+1][0] = r4[2]; bb[2*p4+1][1] = r4[3];
                }
                if (n0 == 0) ldm_x2(bb[8], b2_base + (SM_B_LO - SM_B_HI) + bc);
                // pass3: Ah*Bl
                #pragma unroll
                for (int nt = 0; nt < 9; ++nt)
                    if (nt < 8 || n0 == 0) {
                        mma16816(acc[0][nt], ah[0], bb[nt]);
                        mma16816(acc[1][nt], ah[1], bb[nt]);
                    }
            }

            // ---- epilogue: bias + exact d_chi tail; a1 -> gmem, 128..131 -> Th ----
            {
                const float* Dc = (const float*)(smem + SM_DC + p * 2048);
                float* Th = (float*)(smem + SM_TH);
                #pragma unroll
                for (int mt = 0; mt < 2; ++mt) {
                    const int r = m0 + mt * 16 + tr;
                    const long long rowA = row0 + r;
                    const long long rowB = rowA + 8;
                    const float4 dca = *(const float4*)&Dc[r * 4];
                    const float4 dcb = *(const float4*)&Dc[(r + 8) * 4];
                    #pragma unroll
                    for (int nt = 0; nt < 9; ++nt) {
                        const int c = n0 + nt * 8 + tc;
                        if (c < NCOLS) {
                            float2 bi = *(const float2*)&Bs[c];
                            float4 w0 = *(const float4*)&Wt2[c * 4];
                            float4 w1 = *(const float4*)&Wt2[(c + 1) * 4];
                            float h0 = acc[mt][nt][0] + bi.x;
                            float h1 = acc[mt][nt][1] + bi.y;
                            float h2 = acc[mt][nt][2] + bi.x;
                            float h3 = acc[mt][nt][3] + bi.y;
                            h0 = fmaf(dca.x, w0.x, h0); h0 = fmaf(dca.y, w0.y, h0);
                            h0 = fmaf(dca.z, w0.z, h0); h0 = fmaf(dca.w, w0.w, h0);
                            h1 = fmaf(dca.x, w1.x, h1); h1 = fmaf(dca.y, w1.y, h1);
                            h1 = fmaf(dca.z, w1.z, h1); h1 = fmaf(dca.w, w1.w, h1);
                            h2 = fmaf(dcb.x, w0.x, h2); h2 = fmaf(dcb.y, w0.y, h2);
                            h2 = fmaf(dcb.z, w0.z, h2); h2 = fmaf(dcb.w, w0.w, h2);
                            h3 = fmaf(dcb.x, w1.x, h3); h3 = fmaf(dcb.y, w1.y, h3);
                            h3 = fmaf(dcb.z, w1.z, h3); h3 = fmaf(dcb.w, w1.w, h3);
                            if (c < 128) {
                                if (rowA < n) *(float2*)(out1 + rowA * 128 + c) = make_float2(h0, h1);
                                if (rowB < n) *(float2*)(out1 + rowB * 128 + c) = make_float2(h2, h3);
                            } else {
                                *(float2*)&Th[r * 4 + (c - 128)]       = make_float2(h0, h1);
                                *(float2*)&Th[(r + 8) * 4 + (c - 128)] = make_float2(h2, h3);
                            }
                        }
                    }
                }
            }
            // consumers-only barrier: Th complete
            asm volatile("bar.sync 1, %0;" :: "n"(NCONS) : "memory");

            // ---- chi_out (chi LDG, L2-hot) ----
            {
                const float* Th = (const float*)(smem + SM_TH);
                #pragma unroll
                for (int it = 0; it < 8; ++it) {
                    int i = tid + NCONS * it;     // 0..2047
                    int r = i >> 4;
                    int m = i & 15;
                    long long row = row0 + r;
                    if (row < n) {
                        int s = (m == 0) ? 0 : (m < 4) ? 1 : (m < 9) ? 2 : 3;
                        out2[row * 16 + m] = Th[r * 4 + s] * chi[row * 16 + m];
                    }
                }
            }
        } else {
            // ---- producers: fill the other buffer with tile t+grid ----
            if (tn < ntiles)
                produce_tile(x, chi, n, (long long)tn * TM, smem, sb, p ^ 1, tid - NCONS);
        }

        __syncthreads();
        p ^= 1;
        t = tn;
    }
}

extern "C" void kernel_launch(void* const* d_in, const int* in_sizes, int n_in,
                              void* d_out, int out_size)
{
    const float* x   = (const float*)d_in[0];
    const float* chi = (const float*)d_in[1];
    // d_in[2] = point_mask (unused by reference computation)
    const float* W   = (const float*)d_in[3];
    const float* b   = (const float*)d_in[4];
    float* out = (float*)d_out;

    const int n = in_sizes[2];
    const int ntiles = (n + TM - 1) / TM;

    int dev = 0, nsm = 148;
    cudaGetDevice(&dev);
    cudaDeviceGetAttribute(&nsm, cudaDevAttrMultiProcessorCount, dev);

    cudaFuncSetAttribute(ib_pk,
                         cudaFuncAttributeMaxDynamicSharedMemorySize, SMEM_BYTES);

    prep_kernel<<<64, 256>>>(W, b);
    int grid = ntiles < nsm ? ntiles : nsm;
    ib_pk<<<grid, THREADS, SMEM_BYTES>>>(x, chi, out, n, ntiles);
}